// round 1
// baseline (speedup 1.0000x reference)
#include <cuda_runtime.h>
#include <cuda_bf16.h>

// Problem constants
#define B_   2
#define S_   2048
#define D_   1024
#define H_   16
#define HD_  64
#define M_   (B_ * S_)   // 4096
#define GN   D_          // 1024
#define GK   D_          // 1024

// Scratch (no allocations allowed -> __device__ globals)
__device__ float g_Q[B_ * H_ * S_ * HD_];
__device__ float g_K[B_ * H_ * S_ * HD_];
__device__ float g_V[B_ * H_ * S_ * HD_];
__device__ float g_ctx[B_ * S_ * D_];

// ---------------------------------------------------------------------------
// SGEMM: C = A[M,K] @ W[K,N] + bias, 128x128 block tile, 8x8 microtile.
// mode 0: C row-major [M,N]
// mode 1: scatter into [B,H,S,hd] head layout (for Q/K/V)
// ---------------------------------------------------------------------------
__global__ __launch_bounds__(256) void sgemm_bias(
    const float* __restrict__ A, const float* __restrict__ W,
    const float* __restrict__ bias, float* __restrict__ C, int mode)
{
    __shared__ float As[8][128];
    __shared__ float Bs[8][128];

    const int tid = threadIdx.x;
    const int bx = blockIdx.x, by = blockIdx.y;
    const int ty = tid >> 4, tx = tid & 15;

    const int arow = tid >> 1;            // 0..127
    const int acol = (tid & 1) * 4;       // 0 or 4
    const int brow = tid >> 5;            // 0..7
    const int bcol = (tid & 31) * 4;      // 0..124

    const float* Ag = A + (size_t)(by * 128 + arow) * GK + acol;
    const float* Wg = W + (size_t)brow * GN + bx * 128 + bcol;

    float acc[8][8];
#pragma unroll
    for (int i = 0; i < 8; i++)
#pragma unroll
        for (int j = 0; j < 8; j++) acc[i][j] = 0.0f;

    for (int k0 = 0; k0 < GK; k0 += 8) {
        float4 a = *(const float4*)(Ag + k0);
        As[acol + 0][arow] = a.x;
        As[acol + 1][arow] = a.y;
        As[acol + 2][arow] = a.z;
        As[acol + 3][arow] = a.w;
        float4 b = *(const float4*)(Wg + (size_t)k0 * GN);
        *(float4*)&Bs[brow][bcol] = b;
        __syncthreads();

#pragma unroll
        for (int k = 0; k < 8; k++) {
            float ra[8], rb[8];
            *(float4*)(ra)     = *(const float4*)&As[k][ty * 8];
            *(float4*)(ra + 4) = *(const float4*)&As[k][ty * 8 + 4];
            *(float4*)(rb)     = *(const float4*)&Bs[k][tx * 8];
            *(float4*)(rb + 4) = *(const float4*)&Bs[k][tx * 8 + 4];
#pragma unroll
            for (int i = 0; i < 8; i++)
#pragma unroll
                for (int j = 0; j < 8; j++)
                    acc[i][j] += ra[i] * rb[j];
        }
        __syncthreads();
    }

    // Epilogue: add bias, write out
#pragma unroll
    for (int i = 0; i < 8; i++) {
        const int row = by * 128 + ty * 8 + i;   // m index
#pragma unroll
        for (int j4 = 0; j4 < 2; j4++) {
            const int col = bx * 128 + tx * 8 + j4 * 4;   // n index
            float4 v;
            v.x = acc[i][j4 * 4 + 0] + bias[col + 0];
            v.y = acc[i][j4 * 4 + 1] + bias[col + 1];
            v.z = acc[i][j4 * 4 + 2] + bias[col + 2];
            v.w = acc[i][j4 * 4 + 3] + bias[col + 3];
            if (mode == 0) {
                *(float4*)&C[(size_t)row * GN + col] = v;
            } else {
                const int b = row >> 11;        // /2048
                const int s = row & 2047;
                const int h = col >> 6;         // /64
                const int d = col & 63;
                size_t off = ((((size_t)b * H_ + h) * S_ + s) << 6) + d;
                *(float4*)&C[off] = v;
            }
        }
    }
}

// ---------------------------------------------------------------------------
// Flash-attention (fp32, online softmax). One CTA per (b,h,q-tile of 64).
// SMEM layout: sQ[d][i], sK[d][j] (d-major for QK^T), sV[j][d], sS[j][i]
// (scores transposed -> conflict-free softmax row scans + P.V matmul).
// ---------------------------------------------------------------------------
__global__ __launch_bounds__(256) void attn_kernel(
    const float* __restrict__ Q, const float* __restrict__ K,
    const float* __restrict__ V, const float* __restrict__ mask,
    float* __restrict__ ctx)
{
    extern __shared__ float sm[];
    float* sQ   = sm;            // 64x64 [d][i]
    float* sK   = sm + 4096;     // 64x64 [d][j]
    float* sV   = sm + 8192;     // 64x64 [j][d]
    float* sS   = sm + 12288;    // 64x64 [j][i]
    float* rowm = sm + 16384;    // 64
    float* rowl = rowm + 64;     // 64
    float* rowa = rowl + 64;     // 64 (alpha)
    float* kmadd = rowa + 64;    // 64 (pad-mask additive)

    const int tid = threadIdx.x;
    const int ty = tid >> 4, tx = tid & 15;
    const int q0 = blockIdx.x * 64;
    const int bh = blockIdx.y;
    const int b = bh >> 4;
    const int h = bh & 15;

    const float* Qb = Q + (size_t)bh * S_ * HD_;
    const float* Kb = K + (size_t)bh * S_ * HD_;
    const float* Vb = V + (size_t)bh * S_ * HD_;

    // Load Q tile transposed: sQ[d][i]
#pragma unroll
    for (int it = 0; it < 4; it++) {
        int idx = tid + it * 256;
        int i = idx >> 4;
        int d4 = (idx & 15) * 4;
        float4 a = *(const float4*)(Qb + (size_t)(q0 + i) * HD_ + d4);
        sQ[(d4 + 0) * 64 + i] = a.x;
        sQ[(d4 + 1) * 64 + i] = a.y;
        sQ[(d4 + 2) * 64 + i] = a.z;
        sQ[(d4 + 3) * 64 + i] = a.w;
    }
    if (tid < 64) { rowm[tid] = -1e30f; rowl[tid] = 0.0f; }

    float o[4][4];
#pragma unroll
    for (int i = 0; i < 4; i++)
#pragma unroll
        for (int j = 0; j < 4; j++) o[i][j] = 0.0f;

    const int ntile = (q0 >> 6) + 1;   // causal: only tiles at/below diagonal
    for (int kt = 0; kt < ntile; kt++) {
        const int k0 = kt * 64;
        __syncthreads();   // previous iter readers done; also covers Q load

        // Load K (transposed) and V tiles
#pragma unroll
        for (int it = 0; it < 4; it++) {
            int idx = tid + it * 256;
            int j = idx >> 4;
            int d4 = (idx & 15) * 4;
            float4 a = *(const float4*)(Kb + (size_t)(k0 + j) * HD_ + d4);
            sK[(d4 + 0) * 64 + j] = a.x;
            sK[(d4 + 1) * 64 + j] = a.y;
            sK[(d4 + 2) * 64 + j] = a.z;
            sK[(d4 + 3) * 64 + j] = a.w;
            float4 v = *(const float4*)(Vb + (size_t)(k0 + j) * HD_ + d4);
            *(float4*)&sV[j * 64 + d4] = v;
        }
        if (tid < 64)
            kmadd[tid] = (1.0f - mask[b * S_ + k0 + tid]) * -10000.0f;
        __syncthreads();

        // S = Q.K^T  (4x4 microtile per thread)
        float s[4][4];
#pragma unroll
        for (int i = 0; i < 4; i++)
#pragma unroll
            for (int j = 0; j < 4; j++) s[i][j] = 0.0f;
#pragma unroll 8
        for (int d = 0; d < 64; d++) {
            float ra[4], rb[4];
            *(float4*)ra = *(const float4*)&sQ[d * 64 + ty * 4];
            *(float4*)rb = *(const float4*)&sK[d * 64 + tx * 4];
#pragma unroll
            for (int i = 0; i < 4; i++)
#pragma unroll
                for (int j = 0; j < 4; j++)
                    s[i][j] += ra[i] * rb[j];
        }

        // scale + causal + pad mask, write transposed sS[j][i]
#pragma unroll
        for (int jj = 0; jj < 4; jj++) {
            const int j = tx * 4 + jj;
            const int kg = k0 + j;
            const float madd = kmadd[j];
#pragma unroll
            for (int ii = 0; ii < 4; ii++) {
                const int qg = q0 + ty * 4 + ii;
                float val = s[ii][jj] * 0.125f + madd;   // 1/sqrt(64)
                if (kg > qg) val += -1e10f;
                sS[j * 64 + ty * 4 + ii] = val;
            }
        }
        __syncthreads();

        // Online softmax: one thread per row (conflict-free: bank = row)
        if (tid < 64) {
            const int r = tid;
            float mo = rowm[r], m = mo;
#pragma unroll 8
            for (int j = 0; j < 64; j++) m = fmaxf(m, sS[j * 64 + r]);
            float alpha = __expf(mo - m);
            float l = rowl[r] * alpha;
#pragma unroll 8
            for (int j = 0; j < 64; j++) {
                float p = __expf(sS[j * 64 + r] - m);
                sS[j * 64 + r] = p;
                l += p;
            }
            rowm[r] = m; rowl[r] = l; rowa[r] = alpha;
        }
        __syncthreads();

        // Rescale accumulators, then O += P.V
        float al[4];
#pragma unroll
        for (int ii = 0; ii < 4; ii++) al[ii] = rowa[ty * 4 + ii];
#pragma unroll
        for (int ii = 0; ii < 4; ii++)
#pragma unroll
            for (int jj = 0; jj < 4; jj++) o[ii][jj] *= al[ii];

#pragma unroll 8
        for (int j = 0; j < 64; j++) {
            float rp[4], rv[4];
            *(float4*)rp = *(const float4*)&sS[j * 64 + ty * 4];
            *(float4*)rv = *(const float4*)&sV[j * 64 + tx * 4];
#pragma unroll
            for (int ii = 0; ii < 4; ii++)
#pragma unroll
                for (int jj = 0; jj < 4; jj++)
                    o[ii][jj] += rp[ii] * rv[jj];
        }
    }

    // Normalize and write ctx in [B,S,D] layout
    float inv[4];
#pragma unroll
    for (int ii = 0; ii < 4; ii++) inv[ii] = 1.0f / rowl[ty * 4 + ii];
#pragma unroll
    for (int ii = 0; ii < 4; ii++) {
        const int srow = q0 + ty * 4 + ii;
        float4 v;
        v.x = o[ii][0] * inv[ii];
        v.y = o[ii][1] * inv[ii];
        v.z = o[ii][2] * inv[ii];
        v.w = o[ii][3] * inv[ii];
        size_t off = ((size_t)b * S_ + srow) * D_ + h * HD_ + tx * 4;
        *(float4*)&ctx[off] = v;
    }
}

// ---------------------------------------------------------------------------
extern "C" void kernel_launch(void* const* d_in, const int* in_sizes, int n_in,
                              void* d_out, int out_size)
{
    const float* X    = (const float*)d_in[0];
    const float* mask = (const float*)d_in[1];
    const float* Wq   = (const float*)d_in[2];
    const float* bq   = (const float*)d_in[3];
    const float* Wk   = (const float*)d_in[4];
    const float* bk   = (const float*)d_in[5];
    const float* Wv   = (const float*)d_in[6];
    const float* bv   = (const float*)d_in[7];
    const float* Wo   = (const float*)d_in[8];
    const float* bo   = (const float*)d_in[9];
    float* out = (float*)d_out;

    float *pQ, *pK, *pV, *pctx;
    cudaGetSymbolAddress((void**)&pQ, g_Q);
    cudaGetSymbolAddress((void**)&pK, g_K);
    cudaGetSymbolAddress((void**)&pV, g_V);
    cudaGetSymbolAddress((void**)&pctx, g_ctx);

    const int ATTN_SMEM = (4 * 4096 + 4 * 64) * (int)sizeof(float);  // 66560
    cudaFuncSetAttribute(attn_kernel,
                         cudaFuncAttributeMaxDynamicSharedMemorySize, ATTN_SMEM);

    dim3 gg(GN / 128, M_ / 128);   // (8, 32)

    sgemm_bias<<<gg, 256>>>(X, Wq, bq, pQ, 1);
    sgemm_bias<<<gg, 256>>>(X, Wk, bk, pK, 1);
    sgemm_bias<<<gg, 256>>>(X, Wv, bv, pV, 1);

    dim3 ga(S_ / 64, B_ * H_);     // (32, 32)
    attn_kernel<<<ga, 256, ATTN_SMEM>>>(pQ, pK, pV, mask, pctx);

    sgemm_bias<<<gg, 256>>>(pctx, Wo, bo, out, 0);
}

// round 3
// speedup vs baseline: 1.4720x; 1.4720x over previous
#include <cuda_runtime.h>
#include <cuda_bf16.h>
#include <cstdint>

// Problem constants
#define B_   2
#define S_   2048
#define D_   1024
#define H_   16
#define HD_  64
#define M_   (B_ * S_)   // 4096
#define GN   D_          // 1024
#define GK   D_          // 1024

// ---------------------------------------------------------------------------
// Scratch (no allocations allowed -> __device__ globals)
// ---------------------------------------------------------------------------
__device__ float g_Q[B_ * H_ * S_ * HD_];
__device__ float g_K[B_ * H_ * S_ * HD_];
__device__ float g_V[B_ * H_ * S_ * HD_];
__device__ float g_ctx[B_ * S_ * D_];

__device__ __nv_bfloat16 g_Ahi[M_ * GK];        // hi/lo split of X / ctx
__device__ __nv_bfloat16 g_Alo[M_ * GK];
__device__ __nv_bfloat16 g_Whi[4][GK * GN];     // weights transposed [N][K]
__device__ __nv_bfloat16 g_Wlo[4][GK * GN];

// ---------------------------------------------------------------------------
// PTX helpers (all arch-agnostic: sm_80+ features, compile under compute_103)
// ---------------------------------------------------------------------------
__device__ __forceinline__ uint32_t smem_u32(const void* p) {
    uint32_t a;
    asm("{ .reg .u64 t; cvta.to.shared.u64 t, %1; cvt.u32.u64 %0, t; }"
        : "=r"(a) : "l"(p));
    return a;
}

#define SW(o) ((o) ^ (((o) >> 3) & 0x70))   // SW128 swizzle (Swizzle<3,4,3>)

__device__ __forceinline__ void cp16(uint32_t d, const void* g) {
    asm volatile("cp.async.cg.shared.global [%0], [%1], 16;"
                 :: "r"(d), "l"(g) : "memory");
}
#define CP_COMMIT() asm volatile("cp.async.commit_group;" ::: "memory")
#define CP_WAIT2()  asm volatile("cp.async.wait_group 2;" ::: "memory")

__device__ __forceinline__ void ldsm4(uint32_t& r0, uint32_t& r1,
                                      uint32_t& r2, uint32_t& r3, uint32_t a) {
    asm volatile("ldmatrix.sync.aligned.m8n8.x4.shared.b16 {%0,%1,%2,%3}, [%4];"
                 : "=r"(r0), "=r"(r1), "=r"(r2), "=r"(r3) : "r"(a));
}

__device__ __forceinline__ void mma_bf16(float* c, const uint32_t* a,
                                         uint32_t b0, uint32_t b1) {
    asm volatile(
        "mma.sync.aligned.m16n8k16.row.col.f32.bf16.bf16.f32 "
        "{%0,%1,%2,%3}, {%4,%5,%6,%7}, {%8,%9}, {%0,%1,%2,%3};"
        : "+f"(c[0]), "+f"(c[1]), "+f"(c[2]), "+f"(c[3])
        : "r"(a[0]), "r"(a[1]), "r"(a[2]), "r"(a[3]), "r"(b0), "r"(b1));
}

// ---------------------------------------------------------------------------
// Conversion kernels
// ---------------------------------------------------------------------------
__global__ __launch_bounds__(256) void split_bf16_kernel(
    const float* __restrict__ in, __nv_bfloat16* __restrict__ hi,
    __nv_bfloat16* __restrict__ lo)
{
    int i = blockIdx.x * 256 + threadIdx.x;
    float4 v = ((const float4*)in)[i];
    __nv_bfloat16 h0 = __float2bfloat16(v.x);
    __nv_bfloat16 h1 = __float2bfloat16(v.y);
    __nv_bfloat16 h2 = __float2bfloat16(v.z);
    __nv_bfloat16 h3 = __float2bfloat16(v.w);
    __nv_bfloat16 l0 = __float2bfloat16(v.x - __bfloat162float(h0));
    __nv_bfloat16 l1 = __float2bfloat16(v.y - __bfloat162float(h1));
    __nv_bfloat16 l2 = __float2bfloat16(v.z - __bfloat162float(h2));
    __nv_bfloat16 l3 = __float2bfloat16(v.w - __bfloat162float(h3));
    __nv_bfloat162* H = (__nv_bfloat162*)hi;
    __nv_bfloat162* L = (__nv_bfloat162*)lo;
    H[2 * i]     = __nv_bfloat162(h0, h1);
    H[2 * i + 1] = __nv_bfloat162(h2, h3);
    L[2 * i]     = __nv_bfloat162(l0, l1);
    L[2 * i + 1] = __nv_bfloat162(l2, l3);
}

// W [K][N] f32 -> Whi/Wlo [N][K] bf16 (transpose + split)
__global__ __launch_bounds__(256) void transpose_split_w(
    const float* __restrict__ W, __nv_bfloat16* __restrict__ whi,
    __nv_bfloat16* __restrict__ wlo)
{
    __shared__ float t[32][33];
    const int n0 = blockIdx.x * 32, k0 = blockIdx.y * 32;
    const int tx = threadIdx.x, ty = threadIdx.y;   // (32, 8)
#pragma unroll
    for (int i = 0; i < 32; i += 8)
        t[ty + i][tx] = W[(size_t)(k0 + ty + i) * GN + n0 + tx];
    __syncthreads();
#pragma unroll
    for (int i = 0; i < 32; i += 8) {
        float v = t[tx][ty + i];
        __nv_bfloat16 h = __float2bfloat16(v);
        __nv_bfloat16 l = __float2bfloat16(v - __bfloat162float(h));
        size_t off = (size_t)(n0 + ty + i) * GK + k0 + tx;
        whi[off] = h;
        wlo[off] = l;
    }
}

// ---------------------------------------------------------------------------
// bf16 mma.sync GEMM with 3-pass hi/lo split:
//   C = Ahi@Whi^T + Ahi@Wlo^T + Alo@Whi^T + bias  (W stored [N][K])
// 128x128 CTA tile, 8 warps (32x64 each), K-chunks of 64, 3-stage cp.async.
// mode 0: row-major [M,N];  mode 1: scatter to [B,H,S,hd]
// ---------------------------------------------------------------------------
#define LOAD_CHUNK(c) do {                                                   \
    int ph_ = (c) >> 4, kc_ = ((c) & 15) * 64;                               \
    const __nv_bfloat16* As_ = (ph_ == 2) ? Alo : Ahi;                       \
    const __nv_bfloat16* Bs_ = (ph_ == 1) ? Blo : Bhi;                       \
    uint32_t st_ = sb + ((c) % 3) * 32768;                                   \
    const __nv_bfloat16* ga_ = As_ + (size_t)(m0 + lrow) * GK + kc_ + lhalf * 32; \
    const __nv_bfloat16* gb_ = Bs_ + (size_t)(n0 + lrow) * GK + kc_ + lhalf * 32; \
    uint32_t ob_ = lrow * 128 + lhalf * 64;                                  \
    _Pragma("unroll")                                                        \
    for (int q_ = 0; q_ < 4; q_++) {                                         \
        cp16(st_ + SW(ob_ + q_ * 16), ga_ + q_ * 8);                         \
        cp16(st_ + 16384 + SW(ob_ + q_ * 16), gb_ + q_ * 8);                 \
    }                                                                        \
} while (0)

__global__ __launch_bounds__(256) void gemm_tc(
    const __nv_bfloat16* __restrict__ Ahi, const __nv_bfloat16* __restrict__ Alo,
    const __nv_bfloat16* __restrict__ Bhi, const __nv_bfloat16* __restrict__ Blo,
    const float* __restrict__ bias, float* __restrict__ C, int mode)
{
    extern __shared__ char smc[];
    const uint32_t sb = smem_u32(smc);
    const int tid = threadIdx.x, lane = tid & 31, wid = tid >> 5;
    const int m0 = blockIdx.y * 128, n0 = blockIdx.x * 128;
    const int wm = (wid & 3) * 32, wn = (wid >> 2) * 64;
    const int lrow = tid >> 1, lhalf = tid & 1;

    float acc[2][8][4];
#pragma unroll
    for (int mi = 0; mi < 2; mi++)
#pragma unroll
        for (int ni = 0; ni < 8; ni++)
#pragma unroll
            for (int r = 0; r < 4; r++) acc[mi][ni][r] = 0.0f;

    // ldmatrix per-lane base byte offsets (within stage, excluding k16 step)
    uint32_t aoff[2], boff[4];
#pragma unroll
    for (int mi = 0; mi < 2; mi++) {
        int r = wm + mi * 16 + (lane & 15);
        aoff[mi] = r * 128 + ((lane >> 4) << 4);
    }
#pragma unroll
    for (int nt = 0; nt < 4; nt++) {
        int n = wn + nt * 16 + (lane & 7) + ((lane >> 4) << 3);
        boff[nt] = n * 128 + (((lane >> 3) & 1) << 4);
    }

    // prologue: prefetch chunks 0,1
    LOAD_CHUNK(0); CP_COMMIT();
    LOAD_CHUNK(1); CP_COMMIT();

    for (int c = 0; c < 48; c++) {
        if (c + 2 < 48) LOAD_CHUNK(c + 2);
        CP_COMMIT();
        CP_WAIT2();              // chunk c resident
        __syncthreads();

        const uint32_t sa = sb + (c % 3) * 32768;
        const uint32_t sB = sa + 16384;
#pragma unroll
        for (int k16 = 0; k16 < 4; k16++) {
            const uint32_t kb = k16 * 32;
            uint32_t a[2][4];
            ldsm4(a[0][0], a[0][1], a[0][2], a[0][3], sa + SW(aoff[0] + kb));
            ldsm4(a[1][0], a[1][1], a[1][2], a[1][3], sa + SW(aoff[1] + kb));
            uint32_t bf[4][4];
#pragma unroll
            for (int nt = 0; nt < 4; nt++)
                ldsm4(bf[nt][0], bf[nt][1], bf[nt][2], bf[nt][3],
                      sB + SW(boff[nt] + kb));
#pragma unroll
            for (int mi = 0; mi < 2; mi++)
#pragma unroll
                for (int ni = 0; ni < 8; ni++)
                    mma_bf16(acc[mi][ni], a[mi],
                             bf[ni >> 1][(ni & 1) * 2],
                             bf[ni >> 1][(ni & 1) * 2 + 1]);
        }
        __syncthreads();
    }

    // Epilogue: bias + store
    const int r0 = lane >> 2, cq = (lane & 3) * 2;
#pragma unroll
    for (int mi = 0; mi < 2; mi++) {
#pragma unroll
        for (int ni = 0; ni < 8; ni++) {
            const int rr = m0 + wm + mi * 16 + r0;
            const int cc = n0 + wn + ni * 8 + cq;
            const float2 bv = *(const float2*)&bias[cc];
            float2 v0 = {acc[mi][ni][0] + bv.x, acc[mi][ni][1] + bv.y};
            float2 v1 = {acc[mi][ni][2] + bv.x, acc[mi][ni][3] + bv.y};
            if (mode == 0) {
                *(float2*)&C[(size_t)rr * GN + cc] = v0;
                *(float2*)&C[(size_t)(rr + 8) * GN + cc] = v1;
            } else {
                const int h = cc >> 6, d = cc & 63;
                const int b0i = rr >> 11, s0i = rr & 2047;
                *(float2*)&C[((((size_t)b0i * H_ + h) * S_ + s0i) << 6) + d] = v0;
                const int b1i = (rr + 8) >> 11, s1i = (rr + 8) & 2047;
                *(float2*)&C[((((size_t)b1i * H_ + h) * S_ + s1i) << 6) + d] = v1;
            }
        }
    }
}

// ---------------------------------------------------------------------------
// Flash-attention v2: 128q x 64k tiles, 8x4 microtile, register softmax
// via 16-lane shfl butterflies. Heavy (high-q) tiles scheduled first.
// ---------------------------------------------------------------------------
__global__ __launch_bounds__(256) void attn_kernel(
    const float* __restrict__ Q, const float* __restrict__ K,
    const float* __restrict__ V, const float* __restrict__ mask,
    float* __restrict__ ctx)
{
    extern __shared__ float sm[];
    float* sQ = sm;              // [64][128]  (d-major)
    float* sK = sm + 8192;       // [64][64]   (d-major)
    float* sV = sm + 12288;      // [64][64]   (j-major)
    float* sS = sm + 16384;      // [64][128]  P^T: [j][i]

    const int tid = threadIdx.x;
    const int ty = tid >> 4, tx = tid & 15;
    const int qt = gridDim.x - 1 - blockIdx.x;   // heavy tiles first
    const int q0 = qt * 128;
    const int bh = blockIdx.y;
    const int b = bh >> 4, h = bh & 15;

    const float* Qb = Q + (size_t)bh * S_ * HD_;
    const float* Kb = K + (size_t)bh * S_ * HD_;
    const float* Vb = V + (size_t)bh * S_ * HD_;

    // Load Q tile transposed: sQ[d][i], i in 0..127
#pragma unroll
    for (int it = 0; it < 8; it++) {
        int idx = tid + it * 256;
        int i = idx >> 4;
        int d4 = (idx & 15) * 4;
        float4 a = *(const float4*)(Qb + (size_t)(q0 + i) * HD_ + d4);
        sQ[(d4 + 0) * 128 + i] = a.x;
        sQ[(d4 + 1) * 128 + i] = a.y;
        sQ[(d4 + 2) * 128 + i] = a.z;
        sQ[(d4 + 3) * 128 + i] = a.w;
    }

    float o[8][4];
    float m_run[8], l_run[8];
#pragma unroll
    for (int ii = 0; ii < 8; ii++) {
        m_run[ii] = -1e30f;
        l_run[ii] = 0.0f;
#pragma unroll
        for (int jj = 0; jj < 4; jj++) o[ii][jj] = 0.0f;
    }

    const int ntile = qt * 2 + 2;
    for (int kt = 0; kt < ntile; kt++) {
        const int k0 = kt * 64;
        __syncthreads();   // prev-iter sS/sK/sV readers done; also covers Q load

        // Load K (transposed) and V tiles
#pragma unroll
        for (int it = 0; it < 4; it++) {
            int idx = tid + it * 256;
            int j = idx >> 4;
            int d4 = (idx & 15) * 4;
            float4 a = *(const float4*)(Kb + (size_t)(k0 + j) * HD_ + d4);
            sK[(d4 + 0) * 64 + j] = a.x;
            sK[(d4 + 1) * 64 + j] = a.y;
            sK[(d4 + 2) * 64 + j] = a.z;
            sK[(d4 + 3) * 64 + j] = a.w;
            float4 v = *(const float4*)(Vb + (size_t)(k0 + j) * HD_ + d4);
            *(float4*)&sV[j * 64 + d4] = v;
        }
        __syncthreads();

        // Pad-mask additive for this thread's 4 k-columns
        float4 mk = *(const float4*)&mask[b * S_ + k0 + tx * 4];
        float madd[4] = {(1.0f - mk.x) * -10000.0f, (1.0f - mk.y) * -10000.0f,
                         (1.0f - mk.z) * -10000.0f, (1.0f - mk.w) * -10000.0f};

        // S = Q.K^T  (8x4 microtile)
        float s[8][4];
#pragma unroll
        for (int ii = 0; ii < 8; ii++)
#pragma unroll
            for (int jj = 0; jj < 4; jj++) s[ii][jj] = 0.0f;
#pragma unroll 4
        for (int d = 0; d < 64; d++) {
            float ra[8], rb[4];
            *(float4*)(ra)     = *(const float4*)&sQ[d * 128 + ty * 8];
            *(float4*)(ra + 4) = *(const float4*)&sQ[d * 128 + ty * 8 + 4];
            *(float4*)(rb)     = *(const float4*)&sK[d * 64 + tx * 4];
#pragma unroll
            for (int ii = 0; ii < 8; ii++)
#pragma unroll
                for (int jj = 0; jj < 4; jj++)
                    s[ii][jj] += ra[ii] * rb[jj];
        }

        // scale + causal + pad mask
#pragma unroll
        for (int ii = 0; ii < 8; ii++) {
            const int qg = q0 + ty * 8 + ii;
#pragma unroll
            for (int jj = 0; jj < 4; jj++) {
                const int kg = k0 + tx * 4 + jj;
                float val = s[ii][jj] * 0.125f + madd[jj];
                if (kg > qg) val += -1e10f;
                s[ii][jj] = val;
            }
        }

        // Register online softmax: butterfly across the 16 tx lanes
#pragma unroll
        for (int ii = 0; ii < 8; ii++) {
            float mx = fmaxf(fmaxf(s[ii][0], s[ii][1]), fmaxf(s[ii][2], s[ii][3]));
            mx = fmaxf(mx, __shfl_xor_sync(0xffffffffu, mx, 8));
            mx = fmaxf(mx, __shfl_xor_sync(0xffffffffu, mx, 4));
            mx = fmaxf(mx, __shfl_xor_sync(0xffffffffu, mx, 2));
            mx = fmaxf(mx, __shfl_xor_sync(0xffffffffu, mx, 1));
            const float mn = fmaxf(m_run[ii], mx);
            const float alpha = __expf(m_run[ii] - mn);
            float ps = 0.0f;
#pragma unroll
            for (int jj = 0; jj < 4; jj++) {
                float p = __expf(s[ii][jj] - mn);
                s[ii][jj] = p;
                ps += p;
            }
            ps += __shfl_xor_sync(0xffffffffu, ps, 8);
            ps += __shfl_xor_sync(0xffffffffu, ps, 4);
            ps += __shfl_xor_sync(0xffffffffu, ps, 2);
            ps += __shfl_xor_sync(0xffffffffu, ps, 1);
            l_run[ii] = l_run[ii] * alpha + ps;
            m_run[ii] = mn;
#pragma unroll
            for (int jj = 0; jj < 4; jj++) o[ii][jj] *= alpha;
        }

        // Store P^T to sS[j][i] (float4 over i)
#pragma unroll
        for (int jj = 0; jj < 4; jj++) {
#pragma unroll
            for (int hh = 0; hh < 2; hh++) {
                float4 pv;
                pv.x = s[hh * 4 + 0][jj];
                pv.y = s[hh * 4 + 1][jj];
                pv.z = s[hh * 4 + 2][jj];
                pv.w = s[hh * 4 + 3][jj];
                *(float4*)&sS[(tx * 4 + jj) * 128 + ty * 8 + hh * 4] = pv;
            }
        }
        __syncthreads();

        // O += P.V
#pragma unroll 4
        for (int j = 0; j < 64; j++) {
            float rp[8], rv[4];
            *(float4*)(rp)     = *(const float4*)&sS[j * 128 + ty * 8];
            *(float4*)(rp + 4) = *(const float4*)&sS[j * 128 + ty * 8 + 4];
            *(float4*)(rv)     = *(const float4*)&sV[j * 64 + tx * 4];
#pragma unroll
            for (int ii = 0; ii < 8; ii++)
#pragma unroll
                for (int jj = 0; jj < 4; jj++)
                    o[ii][jj] += rp[ii] * rv[jj];
        }
    }

    // Normalize and write ctx [B,S,D]
#pragma unroll
    for (int ii = 0; ii < 8; ii++) {
        const float inv = 1.0f / l_run[ii];
        const int srow = q0 + ty * 8 + ii;
        float4 v;
        v.x = o[ii][0] * inv;
        v.y = o[ii][1] * inv;
        v.z = o[ii][2] * inv;
        v.w = o[ii][3] * inv;
        *(float4*)&ctx[((size_t)b * S_ + srow) * D_ + h * HD_ + tx * 4] = v;
    }
}

// ---------------------------------------------------------------------------
extern "C" void kernel_launch(void* const* d_in, const int* in_sizes, int n_in,
                              void* d_out, int out_size)
{
    const float* X    = (const float*)d_in[0];
    const float* mask = (const float*)d_in[1];
    const float* Wq   = (const float*)d_in[2];
    const float* bq   = (const float*)d_in[3];
    const float* Wk   = (const float*)d_in[4];
    const float* bk   = (const float*)d_in[5];
    const float* Wv   = (const float*)d_in[6];
    const float* bv   = (const float*)d_in[7];
    const float* Wo   = (const float*)d_in[8];
    const float* bo   = (const float*)d_in[9];
    float* out = (float*)d_out;

    float *pQ, *pK, *pV, *pctx;
    cudaGetSymbolAddress((void**)&pQ, g_Q);
    cudaGetSymbolAddress((void**)&pK, g_K);
    cudaGetSymbolAddress((void**)&pV, g_V);
    cudaGetSymbolAddress((void**)&pctx, g_ctx);

    __nv_bfloat16 *pAhi, *pAlo, *pWhi, *pWlo;
    cudaGetSymbolAddress((void**)&pAhi, g_Ahi);
    cudaGetSymbolAddress((void**)&pAlo, g_Alo);
    cudaGetSymbolAddress((void**)&pWhi, g_Whi);
    cudaGetSymbolAddress((void**)&pWlo, g_Wlo);

    const int ATTN_SMEM = 24576 * (int)sizeof(float);   // 96 KB
    cudaFuncSetAttribute(attn_kernel,
                         cudaFuncAttributeMaxDynamicSharedMemorySize, ATTN_SMEM);
    const int GEMM_SMEM = 3 * 32768;                    // 96 KB
    cudaFuncSetAttribute(gemm_tc,
                         cudaFuncAttributeMaxDynamicSharedMemorySize, GEMM_SMEM);

    const size_t WSZ = (size_t)GK * GN;
    const float* Ws[4] = {Wq, Wk, Wv, Wo};

    // 1) split X -> bf16 hi/lo
    split_bf16_kernel<<<M_ * GK / 1024, 256>>>(X, pAhi, pAlo);
    // 2) transpose+split all 4 weight matrices
    dim3 tb(32, 8), tg(GN / 32, GK / 32);
    for (int i = 0; i < 4; i++)
        transpose_split_w<<<tg, tb>>>(Ws[i], pWhi + i * WSZ, pWlo + i * WSZ);

    // 3) Q/K/V projections (mma.sync), scatter to head layout
    dim3 gg(GN / 128, M_ / 128);   // (8, 32)
    gemm_tc<<<gg, 256, GEMM_SMEM>>>(pAhi, pAlo, pWhi + 0 * WSZ, pWlo + 0 * WSZ, bq, pQ, 1);
    gemm_tc<<<gg, 256, GEMM_SMEM>>>(pAhi, pAlo, pWhi + 1 * WSZ, pWlo + 1 * WSZ, bk, pK, 1);
    gemm_tc<<<gg, 256, GEMM_SMEM>>>(pAhi, pAlo, pWhi + 2 * WSZ, pWlo + 2 * WSZ, bv, pV, 1);

    // 4) attention
    dim3 ga(S_ / 128, B_ * H_);    // (16, 32)
    attn_kernel<<<ga, 256, ATTN_SMEM>>>(pQ, pK, pV, mask, pctx);

    // 5) split ctx, 6) output projection
    split_bf16_kernel<<<M_ * GK / 1024, 256>>>(pctx, pAhi, pAlo);
    gemm_tc<<<gg, 256, GEMM_SMEM>>>(pAhi, pAlo, pWhi + 3 * WSZ, pWlo + 3 * WSZ, bo, out, 0);
}

// round 4
// speedup vs baseline: 2.6693x; 1.8133x over previous
#include <cuda_runtime.h>
#include <cuda_bf16.h>
#include <cstdint>

// Problem constants
#define B_   2
#define S_   2048
#define D_   1024
#define H_   16
#define HD_  64
#define M_   (B_ * S_)   // 4096
#define GN   D_          // 1024
#define GK   D_          // 1024

// ---------------------------------------------------------------------------
// Scratch (no allocations allowed -> __device__ globals)
// ---------------------------------------------------------------------------
__device__ __nv_bfloat16 g_Ahi[M_ * GK];        // hi/lo split of X, later ctx
__device__ __nv_bfloat16 g_Alo[M_ * GK];
__device__ __nv_bfloat16 g_Whi[4][GK * GN];     // weights transposed [N][K]
__device__ __nv_bfloat16 g_Wlo[4][GK * GN];
__device__ __nv_bfloat16 g_Qh[M_ * D_], g_Ql[M_ * D_];   // head layout [bh][s][d]
__device__ __nv_bfloat16 g_Kh[M_ * D_], g_Kl[M_ * D_];
__device__ __nv_bfloat16 g_Vh[M_ * D_], g_Vl[M_ * D_];

// ---------------------------------------------------------------------------
// PTX helpers (sm_80+ features only; tcgen05 is rejected by this harness's
// compute_103 PTX target)
// ---------------------------------------------------------------------------
__device__ __forceinline__ uint32_t smem_u32(const void* p) {
    uint32_t a;
    asm("{ .reg .u64 t; cvta.to.shared.u64 t, %1; cvt.u32.u64 %0, t; }"
        : "=r"(a) : "l"(p));
    return a;
}

#define SW(o) ((o) ^ (((o) >> 3) & 0x70))   // SW128 swizzle

__device__ __forceinline__ void cp16(uint32_t d, const void* g) {
    asm volatile("cp.async.cg.shared.global [%0], [%1], 16;"
                 :: "r"(d), "l"(g) : "memory");
}
#define CP_COMMIT() asm volatile("cp.async.commit_group;" ::: "memory")
#define CP_WAIT1()  asm volatile("cp.async.wait_group 1;" ::: "memory")
#define CP_WAIT2()  asm volatile("cp.async.wait_group 2;" ::: "memory")

__device__ __forceinline__ void ldsm4(uint32_t& r0, uint32_t& r1,
                                      uint32_t& r2, uint32_t& r3, uint32_t a) {
    asm volatile("ldmatrix.sync.aligned.m8n8.x4.shared.b16 {%0,%1,%2,%3}, [%4];"
                 : "=r"(r0), "=r"(r1), "=r"(r2), "=r"(r3) : "r"(a));
}
__device__ __forceinline__ void ldsm4t(uint32_t* r, uint32_t a) {
    asm volatile("ldmatrix.sync.aligned.m8n8.x4.trans.shared.b16 {%0,%1,%2,%3}, [%4];"
                 : "=r"(r[0]), "=r"(r[1]), "=r"(r[2]), "=r"(r[3]) : "r"(a));
}

__device__ __forceinline__ void mma_bf16(float* c, const uint32_t* a,
                                         uint32_t b0, uint32_t b1) {
    asm volatile(
        "mma.sync.aligned.m16n8k16.row.col.f32.bf16.bf16.f32 "
        "{%0,%1,%2,%3}, {%4,%5,%6,%7}, {%8,%9}, {%0,%1,%2,%3};"
        : "+f"(c[0]), "+f"(c[1]), "+f"(c[2]), "+f"(c[3])
        : "r"(a[0]), "r"(a[1]), "r"(a[2]), "r"(a[3]), "r"(b0), "r"(b1));
}

// pack two floats to bf16x2 (a -> low half, b -> high half), round-to-nearest
__device__ __forceinline__ uint32_t pack_bf2(float a, float b) {
    uint32_t d;
    asm("cvt.rn.bf16x2.f32 %0, %1, %2;" : "=r"(d) : "f"(b), "f"(a));
    return d;
}

// truncation split of fp32 v: hi = top 16 bits (bf16), residual returned
__device__ __forceinline__ float trunc_split(float v, uint32_t& hi_bits) {
    hi_bits = __float_as_uint(v) & 0xffff0000u;
    return v - __uint_as_float(hi_bits);
}

// ---------------------------------------------------------------------------
// Conversion kernels
// ---------------------------------------------------------------------------
__global__ __launch_bounds__(256) void split_bf16_kernel(
    const float* __restrict__ in, __nv_bfloat16* __restrict__ hi,
    __nv_bfloat16* __restrict__ lo)
{
    int i = blockIdx.x * 256 + threadIdx.x;
    float4 v = ((const float4*)in)[i];
    uint32_t h0, h1, h2, h3;
    float l0 = trunc_split(v.x, h0);
    float l1 = trunc_split(v.y, h1);
    float l2 = trunc_split(v.z, h2);
    float l3 = trunc_split(v.w, h3);
    uint32_t* H = (uint32_t*)hi;
    uint32_t* L = (uint32_t*)lo;
    H[2 * i]     = __byte_perm(h0, h1, 0x7632);
    H[2 * i + 1] = __byte_perm(h2, h3, 0x7632);
    L[2 * i]     = pack_bf2(l0, l1);
    L[2 * i + 1] = pack_bf2(l2, l3);
}

// W [K][N] f32 -> Whi/Wlo [N][K] bf16 (transpose + split)
__global__ __launch_bounds__(256) void transpose_split_w(
    const float* __restrict__ W, __nv_bfloat16* __restrict__ whi,
    __nv_bfloat16* __restrict__ wlo)
{
    __shared__ float t[32][33];
    const int n0 = blockIdx.x * 32, k0 = blockIdx.y * 32;
    const int tx = threadIdx.x, ty = threadIdx.y;   // (32, 8)
#pragma unroll
    for (int i = 0; i < 32; i += 8)
        t[ty + i][tx] = W[(size_t)(k0 + ty + i) * GN + n0 + tx];
    __syncthreads();
#pragma unroll
    for (int i = 0; i < 32; i += 8) {
        float v = t[tx][ty + i];
        uint32_t hb;
        float l = trunc_split(v, hb);
        size_t off = (size_t)(n0 + ty + i) * GK + k0 + tx;
        whi[off] = __ushort_as_bfloat16((unsigned short)(hb >> 16));
        wlo[off] = __float2bfloat16(l);
    }
}

// ---------------------------------------------------------------------------
// bf16 mma.sync GEMM, 3-pass hi/lo split, 128x128 tile, 8 warps, 3-stage async
// mode 0: fp32 row-major C[M,N]
// mode 1: bf16 hi/lo split outputs scattered to head layout [B,H,S,hd]
// ---------------------------------------------------------------------------
#define LOAD_CHUNK(c) do {                                                   \
    int ph_ = (c) >> 4, kc_ = ((c) & 15) * 64;                               \
    const __nv_bfloat16* As_ = (ph_ == 2) ? Alo : Ahi;                       \
    const __nv_bfloat16* Bs_ = (ph_ == 1) ? Blo : Bhi;                       \
    uint32_t st_ = sb + ((c) % 3) * 32768;                                   \
    const __nv_bfloat16* ga_ = As_ + (size_t)(m0 + lrow) * GK + kc_ + lhalf * 32; \
    const __nv_bfloat16* gb_ = Bs_ + (size_t)(n0 + lrow) * GK + kc_ + lhalf * 32; \
    uint32_t ob_ = lrow * 128 + lhalf * 64;                                  \
    _Pragma("unroll")                                                        \
    for (int q_ = 0; q_ < 4; q_++) {                                         \
        cp16(st_ + SW(ob_ + q_ * 16), ga_ + q_ * 8);                         \
        cp16(st_ + 16384 + SW(ob_ + q_ * 16), gb_ + q_ * 8);                 \
    }                                                                        \
} while (0)

__global__ __launch_bounds__(256) void gemm_tc(
    const __nv_bfloat16* __restrict__ Ahi, const __nv_bfloat16* __restrict__ Alo,
    const __nv_bfloat16* __restrict__ Bhi, const __nv_bfloat16* __restrict__ Blo,
    const float* __restrict__ bias, float* __restrict__ C,
    __nv_bfloat16* __restrict__ Chi, __nv_bfloat16* __restrict__ Clo, int mode)
{
    extern __shared__ char smc[];
    const uint32_t sb = smem_u32(smc);
    const int tid = threadIdx.x, lane = tid & 31, wid = tid >> 5;
    const int m0 = blockIdx.y * 128, n0 = blockIdx.x * 128;
    const int wm = (wid & 3) * 32, wn = (wid >> 2) * 64;
    const int lrow = tid >> 1, lhalf = tid & 1;

    float acc[2][8][4];
#pragma unroll
    for (int mi = 0; mi < 2; mi++)
#pragma unroll
        for (int ni = 0; ni < 8; ni++)
#pragma unroll
            for (int r = 0; r < 4; r++) acc[mi][ni][r] = 0.0f;

    uint32_t aoff[2], boff[4];
#pragma unroll
    for (int mi = 0; mi < 2; mi++) {
        int r = wm + mi * 16 + (lane & 15);
        aoff[mi] = r * 128 + ((lane >> 4) << 4);
    }
#pragma unroll
    for (int nt = 0; nt < 4; nt++) {
        int n = wn + nt * 16 + (lane & 7) + ((lane >> 4) << 3);
        boff[nt] = n * 128 + (((lane >> 3) & 1) << 4);
    }

    LOAD_CHUNK(0); CP_COMMIT();
    LOAD_CHUNK(1); CP_COMMIT();

    for (int c = 0; c < 48; c++) {
        if (c + 2 < 48) LOAD_CHUNK(c + 2);
        CP_COMMIT();
        CP_WAIT2();
        __syncthreads();

        const uint32_t sa = sb + (c % 3) * 32768;
        const uint32_t sB = sa + 16384;
#pragma unroll
        for (int k16 = 0; k16 < 4; k16++) {
            const uint32_t kb = k16 * 32;
            uint32_t a[2][4];
            ldsm4(a[0][0], a[0][1], a[0][2], a[0][3], sa + SW(aoff[0] + kb));
            ldsm4(a[1][0], a[1][1], a[1][2], a[1][3], sa + SW(aoff[1] + kb));
            uint32_t bf[4][4];
#pragma unroll
            for (int nt = 0; nt < 4; nt++)
                ldsm4(bf[nt][0], bf[nt][1], bf[nt][2], bf[nt][3],
                      sB + SW(boff[nt] + kb));
#pragma unroll
            for (int mi = 0; mi < 2; mi++)
#pragma unroll
                for (int ni = 0; ni < 8; ni++)
                    mma_bf16(acc[mi][ni], a[mi],
                             bf[ni >> 1][(ni & 1) * 2],
                             bf[ni >> 1][(ni & 1) * 2 + 1]);
        }
        __syncthreads();
    }

    // Epilogue
    const int r0 = lane >> 2, cq = (lane & 3) * 2;
#pragma unroll
    for (int mi = 0; mi < 2; mi++) {
#pragma unroll
        for (int ni = 0; ni < 8; ni++) {
            const int rr = m0 + wm + mi * 16 + r0;
            const int cc = n0 + wn + ni * 8 + cq;
            const float2 bv = *(const float2*)&bias[cc];
            float v0 = acc[mi][ni][0] + bv.x, v1 = acc[mi][ni][1] + bv.y;
            float v2 = acc[mi][ni][2] + bv.x, v3 = acc[mi][ni][3] + bv.y;
            if (mode == 0) {
                *(float2*)&C[(size_t)rr * GN + cc] = make_float2(v0, v1);
                *(float2*)&C[(size_t)(rr + 8) * GN + cc] = make_float2(v2, v3);
            } else {
                const int h = cc >> 6, d = cc & 63;
                const int bb = rr >> 11;
                const int s0 = rr & 2047, s1 = (rr + 8) & 2047;
                const size_t o0 = ((((size_t)bb * H_ + h) * S_ + s0) << 6) + d;
                const size_t o1 = ((((size_t)bb * H_ + h) * S_ + s1) << 6) + d;
                uint32_t h0, h1, h2, h3;
                float l0 = trunc_split(v0, h0), l1 = trunc_split(v1, h1);
                float l2 = trunc_split(v2, h2), l3 = trunc_split(v3, h3);
                *(uint32_t*)(Chi + o0) = __byte_perm(h0, h1, 0x7632);
                *(uint32_t*)(Chi + o1) = __byte_perm(h2, h3, 0x7632);
                *(uint32_t*)(Clo + o0) = pack_bf2(l0, l1);
                *(uint32_t*)(Clo + o1) = pack_bf2(l2, l3);
            }
        }
    }
}

// ---------------------------------------------------------------------------
// Tensor-core flash attention.
// CTA: 128 q-rows x one (b,h). 8 warps, each 16 q-rows.
// k-tiles of 64, double-buffered (Khi|Klo|Vhi|Vlo = 32KB/stage).
// S = QhiKhi + QhiKlo + QloKhi;  O += PhiVhi + PhiVlo + PloVhi.
// Register-resident online softmax on mma accumulator layout.
// Writes ctx as bf16 hi/lo in [B,S,D] layout (input of Wo gemm).
// ---------------------------------------------------------------------------
#define ATT_STAGE(kt) do {                                                   \
    int s_ = (kt) & 1; int k0_ = (kt) * 64;                                  \
    uint32_t st_ = SST + s_ * 32768;                                         \
    const size_t roff_ = base + (size_t)k0_ * HD_;                           \
    _Pragma("unroll")                                                        \
    for (int i_ = 0; i_ < 2; i_++) {                                         \
        int idx_ = tid + i_ * 256;                                           \
        int r_ = idx_ >> 3, u_ = idx_ & 7;                                   \
        uint32_t so_ = SW((uint32_t)(r_ * 128 + u_ * 16));                   \
        size_t go_ = roff_ + (size_t)r_ * HD_ + u_ * 8;                      \
        cp16(st_ + so_,          Kh_ + go_);                                 \
        cp16(st_ + 8192 + so_,   Kl_ + go_);                                 \
        cp16(st_ + 16384 + so_,  Vh_ + go_);                                 \
        cp16(st_ + 24576 + so_,  Vl_ + go_);                                 \
    }                                                                        \
    if (tid < 64)                                                            \
        smaskf[s_ * 64 + tid] = (1.0f - mask[b * S_ + k0_ + tid]) * -10000.0f; \
} while (0)

__global__ __launch_bounds__(256) void attn_tc(
    const __nv_bfloat16* __restrict__ Qh_, const __nv_bfloat16* __restrict__ Ql_,
    const __nv_bfloat16* __restrict__ Kh_, const __nv_bfloat16* __restrict__ Kl_,
    const __nv_bfloat16* __restrict__ Vh_, const __nv_bfloat16* __restrict__ Vl_,
    const float* __restrict__ mask,
    __nv_bfloat16* __restrict__ ctxh, __nv_bfloat16* __restrict__ ctxl)
{
    extern __shared__ char smraw[];
    const uint32_t sb = smem_u32(smraw);
    const uint32_t SQH = sb, SQL = sb + 16384;
    const uint32_t SST = sb + 32768;                    // 2 stages x 32KB
    float* smaskf = (float*)(smraw + 98304);            // 2 x 64 floats

    const int tid = threadIdx.x, lane = tid & 31, wid = tid >> 5;
    const int qt = gridDim.x - 1 - blockIdx.x;          // heavy tiles first
    const int q0 = qt * 128;
    const int bh = blockIdx.y;
    const int b = bh >> 4, hh = bh & 15;
    const size_t base = (size_t)bh * (S_ * HD_);
    const int wq = wid * 16;

    // Q tile (hi+lo), 128 x 64 bf16, SW128 rows
    {
        const size_t qoff = base + (size_t)q0 * HD_;
#pragma unroll
        for (int i = 0; i < 4; i++) {
            int idx = tid + i * 256;
            int r = idx >> 3, u = idx & 7;
            uint32_t so = SW((uint32_t)(r * 128 + u * 16));
            cp16(SQH + so, Qh_ + qoff + (size_t)r * HD_ + u * 8);
            cp16(SQL + so, Ql_ + qoff + (size_t)r * HD_ + u * 8);
        }
    }
    ATT_STAGE(0);
    CP_COMMIT();           // group 0 = Q + stage 0

    // per-lane fragment addressing
    const uint32_t arow = (wq + (lane & 15)) * 128 + ((lane >> 4) << 4);
    const uint32_t bno  = ((lane & 7) + ((lane >> 4) << 3)) * 128
                        + (((lane >> 3) & 1) << 4);
    const uint32_t vro  = (((lane >> 3) & 1) * 8 + (lane & 7)) * 128
                        + ((lane >> 4) << 4);
    const int c0  = (lane & 3) * 2;
    const int rg0 = q0 + wq + (lane >> 2);
    const int rg1 = rg0 + 8;

    float o[8][4];
#pragma unroll
    for (int ni = 0; ni < 8; ni++)
#pragma unroll
        for (int r = 0; r < 4; r++) o[ni][r] = 0.0f;
    float m0r = -1e30f, m1r = -1e30f, l0r = 0.0f, l1r = 0.0f;

    const int ntile = 2 * qt + 2;
    for (int kt = 0; kt < ntile; kt++) {
        if (kt + 1 < ntile) ATT_STAGE(kt + 1);
        CP_COMMIT();
        CP_WAIT1();
        __syncthreads();

        const int k0 = kt * 64;
        if (k0 <= q0 + wq + 15) {       // skip tiles fully above the diagonal
            const uint32_t sKh = SST + (kt & 1) * 32768;
            const uint32_t sKl = sKh + 8192;
            const uint32_t sVh = sKh + 16384;
            const uint32_t sVl = sKh + 24576;

            float s[8][4];
#pragma unroll
            for (int ni = 0; ni < 8; ni++)
#pragma unroll
                for (int r = 0; r < 4; r++) s[ni][r] = 0.0f;

            // ---- S = Q.K^T (3 split passes) ----
#pragma unroll
            for (int k16 = 0; k16 < 4; k16++) {
                const uint32_t kb = k16 * 32;
                uint32_t aH[4], aL[4], kf[4][4];
                ldsm4(aH[0], aH[1], aH[2], aH[3], SQH + SW(arow + kb));
                ldsm4(aL[0], aL[1], aL[2], aL[3], SQL + SW(arow + kb));
#pragma unroll
                for (int nt = 0; nt < 4; nt++)
                    ldsm4(kf[nt][0], kf[nt][1], kf[nt][2], kf[nt][3],
                          sKh + SW(bno + nt * 2048 + kb));
#pragma unroll
                for (int ni = 0; ni < 8; ni++)
                    mma_bf16(s[ni], aH, kf[ni >> 1][(ni & 1) * 2],
                             kf[ni >> 1][(ni & 1) * 2 + 1]);
#pragma unroll
                for (int ni = 0; ni < 8; ni++)
                    mma_bf16(s[ni], aL, kf[ni >> 1][(ni & 1) * 2],
                             kf[ni >> 1][(ni & 1) * 2 + 1]);
#pragma unroll
                for (int nt = 0; nt < 4; nt++)
                    ldsm4(kf[nt][0], kf[nt][1], kf[nt][2], kf[nt][3],
                          sKl + SW(bno + nt * 2048 + kb));
#pragma unroll
                for (int ni = 0; ni < 8; ni++)
                    mma_bf16(s[ni], aH, kf[ni >> 1][(ni & 1) * 2],
                             kf[ni >> 1][(ni & 1) * 2 + 1]);
            }

            // ---- scale + pad + causal ----
            const float* mrow = smaskf + (kt & 1) * 64;
            const bool needc = (k0 + 63 > q0 + wq);
#pragma unroll
            for (int ni = 0; ni < 8; ni++) {
                const int kg = k0 + ni * 8 + c0;
                const float ma = mrow[ni * 8 + c0];
                const float mb = mrow[ni * 8 + c0 + 1];
                s[ni][0] = s[ni][0] * 0.125f + ma;
                s[ni][1] = s[ni][1] * 0.125f + mb;
                s[ni][2] = s[ni][2] * 0.125f + ma;
                s[ni][3] = s[ni][3] * 0.125f + mb;
                if (needc) {
                    if (kg > rg0)     s[ni][0] -= 1e10f;
                    if (kg + 1 > rg0) s[ni][1] -= 1e10f;
                    if (kg > rg1)     s[ni][2] -= 1e10f;
                    if (kg + 1 > rg1) s[ni][3] -= 1e10f;
                }
            }

            // ---- register online softmax (rows rg0, rg1 per lane) ----
            float mx0 = -1e30f, mx1 = -1e30f;
#pragma unroll
            for (int ni = 0; ni < 8; ni++) {
                mx0 = fmaxf(mx0, fmaxf(s[ni][0], s[ni][1]));
                mx1 = fmaxf(mx1, fmaxf(s[ni][2], s[ni][3]));
            }
            mx0 = fmaxf(mx0, __shfl_xor_sync(0xffffffffu, mx0, 1));
            mx0 = fmaxf(mx0, __shfl_xor_sync(0xffffffffu, mx0, 2));
            mx1 = fmaxf(mx1, __shfl_xor_sync(0xffffffffu, mx1, 1));
            mx1 = fmaxf(mx1, __shfl_xor_sync(0xffffffffu, mx1, 2));
            const float nm0 = fmaxf(m0r, mx0), nm1 = fmaxf(m1r, mx1);
            const float al0 = __expf(m0r - nm0), al1 = __expf(m1r - nm1);
            float ps0 = 0.0f, ps1 = 0.0f;
#pragma unroll
            for (int ni = 0; ni < 8; ni++) {
                s[ni][0] = __expf(s[ni][0] - nm0); ps0 += s[ni][0];
                s[ni][1] = __expf(s[ni][1] - nm0); ps0 += s[ni][1];
                s[ni][2] = __expf(s[ni][2] - nm1); ps1 += s[ni][2];
                s[ni][3] = __expf(s[ni][3] - nm1); ps1 += s[ni][3];
            }
            ps0 += __shfl_xor_sync(0xffffffffu, ps0, 1);
            ps0 += __shfl_xor_sync(0xffffffffu, ps0, 2);
            ps1 += __shfl_xor_sync(0xffffffffu, ps1, 1);
            ps1 += __shfl_xor_sync(0xffffffffu, ps1, 2);
            l0r = l0r * al0 + ps0;  m0r = nm0;
            l1r = l1r * al1 + ps1;  m1r = nm1;
#pragma unroll
            for (int ni = 0; ni < 8; ni++) {
                o[ni][0] *= al0; o[ni][1] *= al0;
                o[ni][2] *= al1; o[ni][3] *= al1;
            }

            // ---- O += P.V (3 split passes) ----
#pragma unroll
            for (int jb = 0; jb < 4; jb++) {
                uint32_t aPh[4], aPl[4];
#pragma unroll
                for (int t = 0; t < 2; t++) {
                    const int ti = jb * 2 + t;
                    uint32_t u0, u1, u2, u3;
                    float l0 = trunc_split(s[ti][0], u0);
                    float l1 = trunc_split(s[ti][1], u1);
                    float l2 = trunc_split(s[ti][2], u2);
                    float l3 = trunc_split(s[ti][3], u3);
                    aPh[t * 2 + 0] = __byte_perm(u0, u1, 0x7632);
                    aPh[t * 2 + 1] = __byte_perm(u2, u3, 0x7632);
                    aPl[t * 2 + 0] = pack_bf2(l0, l1);
                    aPl[t * 2 + 1] = pack_bf2(l2, l3);
                }
                uint32_t vf[4][4];
                const uint32_t vbase = vro + jb * 2048;
#pragma unroll
                for (int nt = 0; nt < 4; nt++)
                    ldsm4t(vf[nt], sVh + SW(vbase + nt * 32));
#pragma unroll
                for (int ni = 0; ni < 8; ni++)
                    mma_bf16(o[ni], aPh, vf[ni >> 1][(ni & 1) * 2],
                             vf[ni >> 1][(ni & 1) * 2 + 1]);
#pragma unroll
                for (int ni = 0; ni < 8; ni++)
                    mma_bf16(o[ni], aPl, vf[ni >> 1][(ni & 1) * 2],
                             vf[ni >> 1][(ni & 1) * 2 + 1]);
#pragma unroll
                for (int nt = 0; nt < 4; nt++)
                    ldsm4t(vf[nt], sVl + SW(vbase + nt * 32));
#pragma unroll
                for (int ni = 0; ni < 8; ni++)
                    mma_bf16(o[ni], aPh, vf[ni >> 1][(ni & 1) * 2],
                             vf[ni >> 1][(ni & 1) * 2 + 1]);
            }
        }
        __syncthreads();
    }

    // ---- normalize + write ctx hi/lo in [B,S,D] layout ----
    const float i0 = 1.0f / l0r, i1 = 1.0f / l1r;
    const size_t row0 = ((size_t)b * S_ + rg0) * D_ + hh * HD_;
    const size_t row1 = ((size_t)b * S_ + rg1) * D_ + hh * HD_;
#pragma unroll
    for (int ni = 0; ni < 8; ni++) {
        const int d = ni * 8 + c0;
        float v0 = o[ni][0] * i0, v1 = o[ni][1] * i0;
        float v2 = o[ni][2] * i1, v3 = o[ni][3] * i1;
        uint32_t u0, u1, u2, u3;
        float l0 = trunc_split(v0, u0), l1 = trunc_split(v1, u1);
        float l2 = trunc_split(v2, u2), l3 = trunc_split(v3, u3);
        *(uint32_t*)(ctxh + row0 + d) = __byte_perm(u0, u1, 0x7632);
        *(uint32_t*)(ctxh + row1 + d) = __byte_perm(u2, u3, 0x7632);
        *(uint32_t*)(ctxl + row0 + d) = pack_bf2(l0, l1);
        *(uint32_t*)(ctxl + row1 + d) = pack_bf2(l2, l3);
    }
}

// ---------------------------------------------------------------------------
extern "C" void kernel_launch(void* const* d_in, const int* in_sizes, int n_in,
                              void* d_out, int out_size)
{
    const float* X    = (const float*)d_in[0];
    const float* mask = (const float*)d_in[1];
    const float* Wq   = (const float*)d_in[2];
    const float* bq   = (const float*)d_in[3];
    const float* Wk   = (const float*)d_in[4];
    const float* bk   = (const float*)d_in[5];
    const float* Wv   = (const float*)d_in[6];
    const float* bv   = (const float*)d_in[7];
    const float* Wo   = (const float*)d_in[8];
    const float* bo   = (const float*)d_in[9];
    float* out = (float*)d_out;

    __nv_bfloat16 *pAh, *pAl, *pWh, *pWl, *pQh, *pQl, *pKh, *pKl, *pVh, *pVl;
    cudaGetSymbolAddress((void**)&pAh, g_Ahi);
    cudaGetSymbolAddress((void**)&pAl, g_Alo);
    cudaGetSymbolAddress((void**)&pWh, g_Whi);
    cudaGetSymbolAddress((void**)&pWl, g_Wlo);
    cudaGetSymbolAddress((void**)&pQh, g_Qh);
    cudaGetSymbolAddress((void**)&pQl, g_Ql);
    cudaGetSymbolAddress((void**)&pKh, g_Kh);
    cudaGetSymbolAddress((void**)&pKl, g_Kl);
    cudaGetSymbolAddress((void**)&pVh, g_Vh);
    cudaGetSymbolAddress((void**)&pVl, g_Vl);

    const int GEMM_SMEM = 3 * 32768;                    // 96 KB
    cudaFuncSetAttribute(gemm_tc,
                         cudaFuncAttributeMaxDynamicSharedMemorySize, GEMM_SMEM);
    const int ATTN_SMEM = 98304 + 512;                  // Q 32K + 2x32K + mask
    cudaFuncSetAttribute(attn_tc,
                         cudaFuncAttributeMaxDynamicSharedMemorySize, ATTN_SMEM);

    const size_t WSZ = (size_t)GK * GN;
    const float* Ws[4] = {Wq, Wk, Wv, Wo};

    split_bf16_kernel<<<M_ * GK / 1024, 256>>>(X, pAh, pAl);
    dim3 tb(32, 8), tg(GN / 32, GK / 32);
    for (int i = 0; i < 4; i++)
        transpose_split_w<<<tg, tb>>>(Ws[i], pWh + i * WSZ, pWl + i * WSZ);

    dim3 gg(GN / 128, M_ / 128);   // (8, 32)
    gemm_tc<<<gg, 256, GEMM_SMEM>>>(pAh, pAl, pWh + 0 * WSZ, pWl + 0 * WSZ,
                                    bq, nullptr, pQh, pQl, 1);
    gemm_tc<<<gg, 256, GEMM_SMEM>>>(pAh, pAl, pWh + 1 * WSZ, pWl + 1 * WSZ,
                                    bk, nullptr, pKh, pKl, 1);
    gemm_tc<<<gg, 256, GEMM_SMEM>>>(pAh, pAl, pWh + 2 * WSZ, pWl + 2 * WSZ,
                                    bv, nullptr, pVh, pVl, 1);

    dim3 ga(S_ / 128, B_ * H_);    // (16, 32)
    attn_tc<<<ga, 256, ATTN_SMEM>>>(pQh, pQl, pKh, pKl, pVh, pVl, mask,
                                    pAh, pAl);   // ctx overwrites X split

    gemm_tc<<<gg, 256, GEMM_SMEM>>>(pAh, pAl, pWh + 3 * WSZ, pWl + 3 * WSZ,
                                    bo, out, nullptr, nullptr, 0);
}